// round 5
// baseline (speedup 1.0000x reference)
#include <cuda_runtime.h>
#include <cuda_fp16.h>
#include <math.h>

#define BATCH 4096
#define FEAT  40960
#define HID   1024
#define HID2  2048
#define NL1   64
#define NL2   32

// ---------------- static device scratch (no allocs allowed) ----------------
__device__ __half g_ftT[(size_t)FEAT * HID];    // 83.9 MB: ft_w^T [FEAT][HID] fp16
__device__ __half g_l1w[(size_t)NL1 * HID2];    // 256 KB: l1_w fp16
__device__ int    g_done;                       // transpose-completion counter

// =========================================================================
// Prep kernel: reset counter + convert l1_w to fp16.  grid 128 x 256.
// =========================================================================
__global__ __launch_bounds__(256) void prep_kernel(const float* __restrict__ l1_w)
{
    const int i = blockIdx.x * 256 + threadIdx.x;     // 32768 threads
#pragma unroll
    for (int u = 0; u < 4; u++)
        g_l1w[i + u * 32768] = __float2half(l1_w[i + u * 32768]);
    if (i == 0) g_done = 0;
}

// =========================================================================
// Mega-kernel:
//   CTAs [0, NT)           : transpose ft_w -> g_ftT (fp16), then signal.
//   CTAs [NT, NT+BATCH)    : scan features -> wait -> gather -> full MLP -> out.
// =========================================================================
#define T1      256
#define NT      512
#define MAXIDX  256
#define NTILE_F (FEAT / 32)                 // 1280
#define NTILES  (NTILE_F * (HID / 64))      // 20480

__global__ __launch_bounds__(T1) void mega_kernel(
    const float* __restrict__ wf,    // [B, FEAT]
    const float* __restrict__ bfeat, // [B, FEAT]
    const float* __restrict__ stm,   // [B, 1]
    const float* __restrict__ ftw,   // [HID, FEAT]
    const float* __restrict__ ft_b,  // [HID]
    const float* __restrict__ l1_b,  // [64]
    const float* __restrict__ l2_w,  // [32, 64]
    const float* __restrict__ l2_b,  // [32]
    const float* __restrict__ l3_w,  // [1, 32]
    const float* __restrict__ l3_b,  // [1]
    float* __restrict__ out, int out_size)
{
    __shared__ union {
        float tile[64][33];                               // transpose staging (8.4 KB)
        struct {
            int   idxW[MAXIDX]; int idxB[MAXIDX];         // 2 KB
            int   cw, cb;
            float h1[HID2];                               // 8 KB
            float h2[NL1];
            float h3[NL2];
        } s;
    } sm;

    const int tid = threadIdx.x;

    if (blockIdx.x < NT) {
        // ---------------- transpose: 40 tiles of 64h x 32f per CTA ----------------
        for (int t = blockIdx.x; t < NTILES; t += NT) {
            const int f0 = (t % NTILE_F) * 32;
            const int h0 = (t / NTILE_F) * 64;
#pragma unroll
            for (int u = 0; u < 8; u++) {
                int idx = tid + u * T1;
                int hl = idx >> 5, fl = idx & 31;
                sm.tile[hl][fl] = __ldcs(ftw + (size_t)(h0 + hl) * FEAT + f0 + fl);
            }
            __syncthreads();
#pragma unroll
            for (int u = 0; u < 4; u++) {
                int idx = tid + u * T1;
                int fl = idx >> 5, hp = idx & 31;
                __half2 v = __floats2half2_rn(sm.tile[2 * hp][fl], sm.tile[2 * hp + 1][fl]);
                *reinterpret_cast<__half2*>(g_ftT + (size_t)(f0 + fl) * HID + h0 + 2 * hp) = v;
            }
            __syncthreads();
        }
        __threadfence();
        __syncthreads();
        if (tid == 0) atomicAdd(&g_done, 1);
        return;
    }

    // ---------------- scan ----------------
    const int b = blockIdx.x - NT;

    if (tid == 0) { sm.s.cw = 0; sm.s.cb = 0; }
    __syncthreads();
    {
        const float4* pw = (const float4*)(wf    + (size_t)b * FEAT);
        const float4* pb = (const float4*)(bfeat + (size_t)b * FEAT);
        for (int base = 0; base < FEAT / 4; base += 4 * T1) {
            float4 v[4], w[4];
#pragma unroll
            for (int u = 0; u < 4; u++) {
                v[u] = __ldcs(pw + base + tid + u * T1);
                w[u] = __ldcs(pb + base + tid + u * T1);
            }
#pragma unroll
            for (int u = 0; u < 4; u++) {
                int i = base + tid + u * T1;
                if (v[u].x != 0.f) { int q = atomicAdd(&sm.s.cw, 1); if (q < MAXIDX) sm.s.idxW[q] = 4*i;   }
                if (v[u].y != 0.f) { int q = atomicAdd(&sm.s.cw, 1); if (q < MAXIDX) sm.s.idxW[q] = 4*i+1; }
                if (v[u].z != 0.f) { int q = atomicAdd(&sm.s.cw, 1); if (q < MAXIDX) sm.s.idxW[q] = 4*i+2; }
                if (v[u].w != 0.f) { int q = atomicAdd(&sm.s.cw, 1); if (q < MAXIDX) sm.s.idxW[q] = 4*i+3; }
                if (w[u].x != 0.f) { int q = atomicAdd(&sm.s.cb, 1); if (q < MAXIDX) sm.s.idxB[q] = 4*i;   }
                if (w[u].y != 0.f) { int q = atomicAdd(&sm.s.cb, 1); if (q < MAXIDX) sm.s.idxB[q] = 4*i+1; }
                if (w[u].z != 0.f) { int q = atomicAdd(&sm.s.cb, 1); if (q < MAXIDX) sm.s.idxB[q] = 4*i+2; }
                if (w[u].w != 0.f) { int q = atomicAdd(&sm.s.cb, 1); if (q < MAXIDX) sm.s.idxB[q] = 4*i+3; }
            }
        }
    }
    __syncthreads();

    // wait for transpose completion (scanners have ~50us of scan work first)
    if (tid == 0) {
        while (atomicAdd(&g_done, 0) < NT) __nanosleep(128);
    }
    __syncthreads();
    __threadfence();

    // ---------------- gather ----------------
    const float4 bias = *reinterpret_cast<const float4*>(ft_b + 4 * tid);
    float4 accW = bias, accB = bias;
    {
        const int nW = min(sm.s.cw, MAXIDX);
#pragma unroll 4
        for (int j = 0; j < nW; j++) {
            const uint2 raw = *reinterpret_cast<const uint2*>(
                g_ftT + (size_t)sm.s.idxW[j] * HID + 4 * tid);
            const float2 lo = __half22float2(*reinterpret_cast<const __half2*>(&raw.x));
            const float2 hi = __half22float2(*reinterpret_cast<const __half2*>(&raw.y));
            accW.x += lo.x; accW.y += lo.y; accW.z += hi.x; accW.w += hi.y;
        }
        const int nB = min(sm.s.cb, MAXIDX);
#pragma unroll 4
        for (int j = 0; j < nB; j++) {
            const uint2 raw = *reinterpret_cast<const uint2*>(
                g_ftT + (size_t)sm.s.idxB[j] * HID + 4 * tid);
            const float2 lo = __half22float2(*reinterpret_cast<const __half2*>(&raw.x));
            const float2 hi = __half22float2(*reinterpret_cast<const __half2*>(&raw.y));
            accB.x += lo.x; accB.y += lo.y; accB.z += hi.x; accB.w += hi.y;
        }
    }

    // stm select + clip -> h1 in smem
    const float s = __ldg(stm + b);
    {
        float cw[4] = {fminf(fmaxf(accW.x,0.f),1.f), fminf(fmaxf(accW.y,0.f),1.f),
                       fminf(fmaxf(accW.z,0.f),1.f), fminf(fmaxf(accW.w,0.f),1.f)};
        float cb[4] = {fminf(fmaxf(accB.x,0.f),1.f), fminf(fmaxf(accB.y,0.f),1.f),
                       fminf(fmaxf(accB.z,0.f),1.f), fminf(fmaxf(accB.w,0.f),1.f)};
#pragma unroll
        for (int j = 0; j < 4; j++) {
            sm.s.h1[4 * tid + j]       = s * cw[j] + (1.f - s) * cb[j];
            sm.s.h1[HID + 4 * tid + j] = s * cb[j] + (1.f - s) * cw[j];
        }
    }
    __syncthreads();

    // ---------------- l1: 8 warps x 8 outputs, shuffle-reduced dots ----------------
    {
        const int w = tid >> 5, l = tid & 31;
#pragma unroll
        for (int oi = 0; oi < 8; oi++) {
            const int o = w * 8 + oi;
            const __half2* wp = reinterpret_cast<const __half2*>(g_l1w + (size_t)o * HID2);
            float acc = 0.f;
#pragma unroll 8
            for (int i = 0; i < HID2 / 64; i++) {       // 32 iters
                const float2 wv = __half22float2(__ldg(wp + l + 32 * i));
                const float2 hv = *reinterpret_cast<const float2*>(&sm.s.h1[2 * (l + 32 * i)]);
                acc = fmaf(hv.x, wv.x, fmaf(hv.y, wv.y, acc));
            }
#pragma unroll
            for (int off = 16; off; off >>= 1)
                acc += __shfl_xor_sync(0xFFFFFFFFu, acc, off);
            if (l == 0)
                sm.s.h2[o] = fminf(fmaxf(acc + __ldg(l1_b + o), 0.f), 1.f);
        }
    }
    __syncthreads();

    // ---------------- l2: warp 0, one output per lane ----------------
    if (tid < NL2) {
        float acc = __ldg(l2_b + tid);
        const float* wrow = l2_w + tid * NL1;
#pragma unroll
        for (int k = 0; k < NL1; k++)
            acc = fmaf(sm.s.h2[k], __ldg(wrow + k), acc);
        sm.s.h3[tid] = fminf(fmaxf(acc, 0.f), 1.f);
    }
    __syncthreads();

    // ---------------- l3 + sigmoid ----------------
    if (tid == 0) {
        float acc = __ldg(l3_b);
#pragma unroll
        for (int k = 0; k < NL2; k++)
            acc = fmaf(sm.s.h3[k], __ldg(l3_w + k), acc);
        const float sig = 1.f / (1.f + expf(-acc));
        if (out_size >= 2 * BATCH) {
            out[b]         = sig;
            out[BATCH + b] = acc;
        } else {
            out[b] = sig;
        }
    }
}

// =========================================================================
extern "C" void kernel_launch(void* const* d_in, const int* in_sizes, int n_in,
                              void* d_out, int out_size)
{
    const float* wf    = (const float*)d_in[0];
    const float* bfeat = (const float*)d_in[1];
    const float* stm   = (const float*)d_in[2];
    const float* ft_w  = (const float*)d_in[3];
    const float* ft_b  = (const float*)d_in[4];
    const float* l1_w  = (const float*)d_in[5];
    const float* l1_b  = (const float*)d_in[6];
    const float* l2_w  = (const float*)d_in[7];
    const float* l2_b  = (const float*)d_in[8];
    const float* l3_w  = (const float*)d_in[9];
    const float* l3_b  = (const float*)d_in[10];
    float* out = (float*)d_out;

    prep_kernel<<<128, 256>>>(l1_w);
    mega_kernel<<<NT + BATCH, T1>>>(wf, bfeat, stm, ft_w, ft_b,
                                    l1_b, l2_w, l2_b, l3_w, l3_b, out, out_size);
}